// round 7
// baseline (speedup 1.0000x reference)
#include <cuda_runtime.h>
#include <cuda_bf16.h>

// GCNet cost-volume + softargmax, algebraically collapsed.
//
//   dmin = min_disp/2, dmax = max_disp/2
//   Left channels: softmax of d-constant => uniform => out = (dmin+dmax-1)/2.
//   Right channels: per-row prefix sums of exp(feaR):
//     P[x] = prefix exp(feaR[x]), Q[x] = prefix x*exp(feaR[x])
//     valid src x in [lo, hi], hi = w-dmin, lo = max(0, w-dmax+1)
//     Sv = P[hi]-P[lo-1];  Tv = w*Sv - (Q[hi]-Q[lo-1])
//     invalid d contribute exp(0)=1: z of them, Tz arithmetic series
//     disp = (Tv+Tz)/(Sv+z)
//
// R6 finding: latency-bound at occ 34.8% — 1 warp/row caps the chip at 4096
// warps (43% of capacity) and the per-warp dependency chain can't be hidden.
// This version: 2 warps per row, 4 cols/thread -> 8192 warps (~85% cap),
// half the per-thread work. Cross-warp scan via one smem total + 2 cheap
// 128-thread barriers. Window lookups (dmin=0,dmax=64): P[w0-64..w0-61] is
// contiguous -> one LDS.128 per array.

#define BW  256   // W
#define HH  128
#define CC  32
#define RPB 2     // rows per block
#define TPR 64    // threads per row (2 warps)
#define NTH (RPB * TPR)

__global__ __launch_bounds__(NTH)
void gcnet_softargmax_kernel(const float* __restrict__ feaR,
                             const int* __restrict__ pmin,
                             const int* __restrict__ pmax,
                             float* __restrict__ out)
{
    __shared__ __align__(16) float sP[RPB][BW];
    __shared__ __align__(16) float sQ[RPB][BW];
    __shared__ float wTe[RPB];
    __shared__ float wTq[RPB];

    const int tid  = threadIdx.x;
    const int rloc = tid >> 6;                 // row within block
    const int t    = tid & 63;                 // thread within row
    const int lane = tid & 31;
    const int wir  = (tid >> 5) & 1;           // warp within row
    const int row  = blockIdx.x * RPB + rloc;  // 0..4095 == c*H + h
    const int w0   = t << 2;                   // first of 4 columns

    const int dmin = pmin[0] / 2;              // non-negative: trunc == floor
    const int dmax = pmax[0] / 2;

    // One 128-bit load: this thread's 4 columns.
    const float4 v = *reinterpret_cast<const float4*>(feaR + ((size_t)row << 8) + w0);

    const float e0 = __expf(v.x);
    const float e1 = __expf(v.y);
    const float e2 = __expf(v.z);
    const float e3 = __expf(v.w);

    // Thread-local inclusive prefixes over 4 elements.
    float ce[4], cq[4];
    ce[0] = e0;             cq[0] = e0 * (float)w0;
    ce[1] = ce[0] + e1;     cq[1] = fmaf(e1, (float)(w0 + 1), cq[0]);
    ce[2] = ce[1] + e2;     cq[2] = fmaf(e2, (float)(w0 + 2), cq[1]);
    ce[3] = ce[2] + e3;     cq[3] = fmaf(e3, (float)(w0 + 3), cq[2]);

    // Warp inclusive scan of per-thread totals (5 double-shfl steps).
    float ie = ce[3], iq = cq[3];
    #pragma unroll
    for (int off = 1; off < 32; off <<= 1) {
        float a = __shfl_up_sync(0xFFFFFFFFu, ie, off);
        float b = __shfl_up_sync(0xFFFFFFFFu, iq, off);
        if (lane >= off) { ie += a; iq += b; }
    }
    float offe = ie - ce[3];        // exclusive prefix within warp (exact 0, lane 0)
    float offq = iq - cq[3];

    // Cross-warp: warp 0's row total -> warp 1.
    if (wir == 0 && lane == 31) { wTe[rloc] = ie; wTq[rloc] = iq; }
    __syncthreads();
    if (wir == 1) { offe += wTe[rloc]; offq += wTq[rloc]; }

    // Full row-inclusive prefixes for this thread's 4 columns.
    float P[4], Q[4];
    #pragma unroll
    for (int k = 0; k < 4; k++) { P[k] = offe + ce[k]; Q[k] = offq + cq[k]; }

    // Publish for window lookups (one STS.128 each).
    *reinterpret_cast<float4*>(&sP[rloc][w0]) = make_float4(P[0], P[1], P[2], P[3]);
    *reinterpret_cast<float4*>(&sQ[rloc][w0]) = make_float4(Q[0], Q[1], Q[2], Q[3]);
    __syncthreads();

    float res[4];

    if (dmin == 0 && dmax == 64) {
        // ---- Specialized path (the shapes this problem runs) ----
        // hi = w -> own register. lo-1 = w-64: contiguous 4 floats -> LDS.128.
        float4 Plo4 = make_float4(0.f, 0.f, 0.f, 0.f);
        float4 Qlo4 = Plo4;
        if (w0 >= 64) {
            Plo4 = *reinterpret_cast<const float4*>(&sP[rloc][w0 - 64]);
            Qlo4 = *reinterpret_cast<const float4*>(&sQ[rloc][w0 - 64]);
        }
        const float pl[4] = {Plo4.x, Plo4.y, Plo4.z, Plo4.w};
        const float ql[4] = {Qlo4.x, Qlo4.y, Qlo4.z, Qlo4.w};
        #pragma unroll
        for (int k = 0; k < 4; k++) {
            const int   w  = w0 + k;
            const float Sv = P[k] - pl[k];
            const float Tv = fmaf((float)w, Sv, -(Q[k] - ql[k]));
            // invalid d: d in [w+1, 64) -> z = max(63-w,0), Tz = (w+64)z/2
            const float zf = (w < 63) ? (float)(63 - w) : 0.0f;
            const float Tz = 0.5f * (float)(w + 64) * zf;
            res[k] = __fdividef(Tv + Tz, Sv + zf);
        }
    } else {
        // ---- Generic fallback ----
        #pragma unroll
        for (int k = 0; k < 4; k++) {
            const int w  = w0 + k;
            const int hi = w - dmin;
            float Sv = 0.0f, Tv = 0.0f;
            if (hi >= 0) {
                int lo = w - dmax + 1;
                if (lo < 0) lo = 0;
                const float Plo = (lo > 0) ? sP[rloc][lo - 1] : 0.0f;
                const float Qlo = (lo > 0) ? sQ[rloc][lo - 1] : 0.0f;
                Sv = sP[rloc][hi] - Plo;
                Tv = fmaf((float)w, Sv, -(sQ[rloc][hi] - Qlo));
            }
            int a = (w + 1 > dmin) ? (w + 1) : dmin;
            int z = dmax - a;
            if (z < 0) z = 0;
            const float Tz = (z > 0) ? 0.5f * (float)(a + dmax - 1) * (float)z : 0.0f;
            res[k] = __fdividef(Tv + Tz, Sv + (float)z);
        }
    }

    const int c = row >> 7;
    const int h = row & 127;
    const size_t plane = (size_t)HH * BW;
    const size_t base  = (size_t)h * BW + w0;
    const float  lc    = 0.5f * (float)(dmin + dmax - 1);

    *reinterpret_cast<float4*>(out + ((size_t)(CC + c)) * plane + base) =
        make_float4(res[0], res[1], res[2], res[3]);
    *reinterpret_cast<float4*>(out + ((size_t)c) * plane + base) =
        make_float4(lc, lc, lc, lc);
}

extern "C" void kernel_launch(void* const* d_in, const int* in_sizes, int n_in,
                              void* d_out, int out_size)
{
    // d_in[0] = feaL (unused — left channels are analytically constant)
    const float* feaR = (const float*)d_in[1];
    const int*   pmin = (const int*)d_in[2];
    const int*   pmax = (const int*)d_in[3];
    float*       out  = (float*)d_out;

    gcnet_softargmax_kernel<<<(CC * HH) / RPB, NTH>>>(feaR, pmin, pmax, out);
}

// round 8
// speedup vs baseline: 1.1106x; 1.1106x over previous
#include <cuda_runtime.h>
#include <cuda_bf16.h>

// GCNet cost-volume + softargmax, algebraically collapsed.
//
//   dmin = min_disp/2, dmax = max_disp/2
//   Left channels: softmax of d-constant => uniform => out = (dmin+dmax-1)/2.
//   Right channels: per-row prefix sums of exp(feaR):
//     P[x] = prefix exp(feaR[x]), Q[x] = prefix x*exp(feaR[x])
//     valid src x in [lo, hi], hi = w-dmin, lo = max(0, w-dmax+1)
//     Sv = P[hi]-P[lo-1];  Tv = w*Sv - (Q[hi]-Q[lo-1])
//     invalid d contribute exp(0)=1: z of them, Tz arithmetic series
//     disp = (Tv+Tz)/(Sv+z)
//
// R7 post-mortem: doubling occupancy (2 warps/row) REGRESSED — the kernel is
// overhead/instruction bound, not occupancy bound. This reverts to the best
// config (1 warp/row, 8 cols/thread, 2-warp blocks) and cuts the window
// phase: the 16 dependent SHFLs are replaced by 4 STS.128 + __syncwarp +
// 4 LDS.128 (P/Q[w0-64..w0-57] are contiguous).

#define BW  256   // W
#define HH  128
#define CC  32
#define RPB 2     // rows (=warps) per block
#define NTH (RPB * 32)

__global__ __launch_bounds__(NTH)
void gcnet_softargmax_kernel(const float* __restrict__ feaR,
                             const int* __restrict__ pmin,
                             const int* __restrict__ pmax,
                             float* __restrict__ out)
{
    __shared__ __align__(16) float sP[RPB][BW];
    __shared__ __align__(16) float sQ[RPB][BW];

    const int tid  = threadIdx.x;
    const int rloc = tid >> 5;                 // warp = row within block
    const int lane = tid & 31;
    const int row  = blockIdx.x * RPB + rloc;  // 0..4095 == c*H + h
    const int w0   = lane << 3;                // first of 8 columns

    const int dmin = pmin[0] / 2;              // non-negative: trunc == floor
    const int dmax = pmax[0] / 2;

    // 2x 128-bit loads: this thread's 8 columns.
    const float* rp0 = feaR + ((size_t)row << 8) + w0;
    const float4 va = *reinterpret_cast<const float4*>(rp0);
    const float4 vb = *reinterpret_cast<const float4*>(rp0 + 4);

    // All exps on MUFU (chip-wide MUFU demand is tiny; never binding).
    const float e0 = __expf(va.x);
    const float e1 = __expf(va.y);
    const float e2 = __expf(va.z);
    const float e3 = __expf(va.w);
    const float e4 = __expf(vb.x);
    const float e5 = __expf(vb.y);
    const float e6 = __expf(vb.z);
    const float e7 = __expf(vb.w);

    // Thread-local inclusive prefixes over 8 elements.
    float ce[8], cq[8];
    ce[0] = e0;             cq[0] = e0 * (float)w0;
    ce[1] = ce[0] + e1;     cq[1] = fmaf(e1, (float)(w0 + 1), cq[0]);
    ce[2] = ce[1] + e2;     cq[2] = fmaf(e2, (float)(w0 + 2), cq[1]);
    ce[3] = ce[2] + e3;     cq[3] = fmaf(e3, (float)(w0 + 3), cq[2]);
    ce[4] = ce[3] + e4;     cq[4] = fmaf(e4, (float)(w0 + 4), cq[3]);
    ce[5] = ce[4] + e5;     cq[5] = fmaf(e5, (float)(w0 + 5), cq[4]);
    ce[6] = ce[5] + e6;     cq[6] = fmaf(e6, (float)(w0 + 6), cq[5]);
    ce[7] = ce[6] + e7;     cq[7] = fmaf(e7, (float)(w0 + 7), cq[6]);

    // Warp inclusive scan of per-thread totals (5 double-shfl steps).
    float ie = ce[7], iq = cq[7];
    #pragma unroll
    for (int off = 1; off < 32; off <<= 1) {
        float a = __shfl_up_sync(0xFFFFFFFFu, ie, off);
        float b = __shfl_up_sync(0xFFFFFFFFu, iq, off);
        if (lane >= off) { ie += a; iq += b; }
    }
    const float offe = ie - ce[7];      // exclusive prefix (exact 0 for lane 0)
    const float offq = iq - cq[7];

    // Full row-inclusive prefixes, in registers; publish to warp-private smem.
    float P[8], Q[8];
    #pragma unroll
    for (int k = 0; k < 8; k++) { P[k] = offe + ce[k]; Q[k] = offq + cq[k]; }

    #pragma unroll
    for (int k = 0; k < 8; k += 4) {
        *reinterpret_cast<float4*>(&sP[rloc][w0 + k]) =
            make_float4(P[k], P[k + 1], P[k + 2], P[k + 3]);
        *reinterpret_cast<float4*>(&sQ[rloc][w0 + k]) =
            make_float4(Q[k], Q[k + 1], Q[k + 2], Q[k + 3]);
    }
    __syncwarp();

    float res[8];

    if (dmin == 0 && dmax == 64) {
        // ---- Specialized path (the shapes this problem runs) ----
        // hi = w -> own register. lo-1 = w-64: 8 contiguous floats -> 2 LDS.128.
        float pl[8], ql[8];
        if (w0 >= 64) {
            const float4 pa = *reinterpret_cast<const float4*>(&sP[rloc][w0 - 64]);
            const float4 pb = *reinterpret_cast<const float4*>(&sP[rloc][w0 - 60]);
            const float4 qa = *reinterpret_cast<const float4*>(&sQ[rloc][w0 - 64]);
            const float4 qb = *reinterpret_cast<const float4*>(&sQ[rloc][w0 - 60]);
            pl[0] = pa.x; pl[1] = pa.y; pl[2] = pa.z; pl[3] = pa.w;
            pl[4] = pb.x; pl[5] = pb.y; pl[6] = pb.z; pl[7] = pb.w;
            ql[0] = qa.x; ql[1] = qa.y; ql[2] = qa.z; ql[3] = qa.w;
            ql[4] = qb.x; ql[5] = qb.y; ql[6] = qb.z; ql[7] = qb.w;
        } else {
            #pragma unroll
            for (int k = 0; k < 8; k++) { pl[k] = 0.0f; ql[k] = 0.0f; }
        }
        #pragma unroll
        for (int k = 0; k < 8; k++) {
            const int   w  = w0 + k;
            const float Sv = P[k] - pl[k];
            const float Tv = fmaf((float)w, Sv, -(Q[k] - ql[k]));
            // invalid d: d in [w+1, 64) -> z = max(63-w,0), Tz = (w+64)z/2
            const float zf = (w < 63) ? (float)(63 - w) : 0.0f;
            const float Tz = 0.5f * (float)(w + 64) * zf;
            res[k] = __fdividef(Tv + Tz, Sv + zf);
        }
    } else {
        // ---- Generic fallback ----
        #pragma unroll
        for (int k = 0; k < 8; k++) {
            const int w  = w0 + k;
            const int hi = w - dmin;
            float Sv = 0.0f, Tv = 0.0f;
            if (hi >= 0) {
                int lo = w - dmax + 1;
                if (lo < 0) lo = 0;
                const float Plo = (lo > 0) ? sP[rloc][lo - 1] : 0.0f;
                const float Qlo = (lo > 0) ? sQ[rloc][lo - 1] : 0.0f;
                Sv = sP[rloc][hi] - Plo;
                Tv = fmaf((float)w, Sv, -(sQ[rloc][hi] - Qlo));
            }
            int a = (w + 1 > dmin) ? (w + 1) : dmin;
            int z = dmax - a;
            if (z < 0) z = 0;
            const float Tz = (z > 0) ? 0.5f * (float)(a + dmax - 1) * (float)z : 0.0f;
            res[k] = __fdividef(Tv + Tz, Sv + (float)z);
        }
    }

    const int c = row >> 7;
    const int h = row & 127;
    const size_t plane = (size_t)HH * BW;
    const size_t base  = (size_t)h * BW + w0;
    const float  lc    = 0.5f * (float)(dmin + dmax - 1);

    float* rp = out + ((size_t)(CC + c)) * plane + base;   // right channels
    float* lp = out + ((size_t)c) * plane + base;          // left channels
    *reinterpret_cast<float4*>(rp)     = make_float4(res[0], res[1], res[2], res[3]);
    *reinterpret_cast<float4*>(rp + 4) = make_float4(res[4], res[5], res[6], res[7]);
    *reinterpret_cast<float4*>(lp)     = make_float4(lc, lc, lc, lc);
    *reinterpret_cast<float4*>(lp + 4) = make_float4(lc, lc, lc, lc);
}

extern "C" void kernel_launch(void* const* d_in, const int* in_sizes, int n_in,
                              void* d_out, int out_size)
{
    // d_in[0] = feaL (unused — left channels are analytically constant)
    const float* feaR = (const float*)d_in[1];
    const int*   pmin = (const int*)d_in[2];
    const int*   pmax = (const int*)d_in[3];
    float*       out  = (float*)d_out;

    gcnet_softargmax_kernel<<<(CC * HH) / RPB, NTH>>>(feaR, pmin, pmax, out);
}